// round 2
// baseline (speedup 1.0000x reference)
#include <cuda_runtime.h>
#include <cstdint>

// Problem constants (fixed shapes from reference)
#define B_  32
#define S_  512
#define H_  768
#define P_  76
#define K_  64
#define E_  768
#define M_  (B_ * P_)     // 2432 rows

// Scratch: dense output (pre-LayerNorm) + normalized int32 indices
__device__ float g_lm[M_ * E_];          // 7.1 MB
__device__ int   g_mpos[M_];
__device__ int   g_cand[M_ * K_];
__device__ int   g_c64;                  // candidate array is int64?

// ---------------------------------------------------------------------------
// Prologue A (1 block): detect dtype of both index arrays; convert mpos.
// int64 little-endian nonneg < 2^31  =>  every odd 32-bit word == 0.
// ---------------------------------------------------------------------------
__global__ void prep_detect_kernel(const int* __restrict__ mraw,
                                   const int* __restrict__ craw)
{
    __shared__ int odd_nz_m, odd_nz_c;
    const int tid = threadIdx.x;
    if (tid == 0) { odd_nz_m = 0; odd_nz_c = 0; }
    __syncthreads();

    // mpos: M_ 32-bit words are safe to read under either dtype
    for (int i = tid; i < M_ / 2; i += 256)
        if (mraw[2 * i + 1] != 0) atomicOr(&odd_nz_m, 1);
    // cand: scan first 4096 pairs (8192 words <= M_*K_ words)
    for (int i = tid; i < 4096; i += 256)
        if (craw[2 * i + 1] != 0) atomicOr(&odd_nz_c, 1);
    __syncthreads();

    const int m64 = (odd_nz_m == 0);
    for (int i = tid; i < M_; i += 256)
        g_mpos[i] = m64 ? mraw[2 * i] : mraw[i];
    if (tid == 0) g_c64 = (odd_nz_c == 0);
}

// ---------------------------------------------------------------------------
// Prologue B (grid): convert candidate indices to int32.
// ---------------------------------------------------------------------------
__global__ void prep_cand_kernel(const int* __restrict__ craw)
{
    const int is64 = g_c64;
    int idx = blockIdx.x * blockDim.x + threadIdx.x;
    if (idx < M_ * K_)
        g_cand[idx] = is64 ? craw[2 * idx] : craw[idx];
}

// ---------------------------------------------------------------------------
// Kernel 1: gathered-A SGEMM.  lm[m, e] = sum_h seq[b, pos, h] * W[h, e] + b[e]
// 128x128 block tile, BK=16, 256 threads, 8x8 per-thread microtile.
// M=2432=19*128, N=768=6*128, K=768=48*16 -> no edge cases.
// ---------------------------------------------------------------------------
__global__ void __launch_bounds__(256, 2)
gemm_gather_kernel(const float* __restrict__ seq,
                   const float* __restrict__ W,
                   const float* __restrict__ bias)
{
    __shared__ float As[16][132];         // transposed A tile, padded
    __shared__ float Bs[16][128];
    __shared__ unsigned rowoff[128];      // element offsets fit in 32 bits (12.6M max)

    const int tid  = threadIdx.x;
    const int row0 = blockIdx.y * 128;
    const int col0 = blockIdx.x * 128;

    if (tid < 128) {
        int m = row0 + tid;
        int b = m / P_;
        int pos = g_mpos[m];
        rowoff[tid] = (unsigned)(b * S_ + pos) * H_;
    }
    __syncthreads();

    float acc[8][8];
#pragma unroll
    for (int i = 0; i < 8; i++)
#pragma unroll
        for (int j = 0; j < 8; j++) acc[i][j] = 0.f;

    const int arow = tid >> 2;            // 0..63
    const int acol = (tid & 3) * 4;       // 0,4,8,12
    const int brow = tid >> 5;            // 0..7
    const int bcol = (tid & 31) * 4;      // 0..124
    const int ty   = tid >> 4;            // 0..15
    const int tx   = tid & 15;            // 0..15

    for (int k0 = 0; k0 < H_; k0 += 16) {
        float4 a0 = *(const float4*)(seq + rowoff[arow]      + k0 + acol);
        float4 a1 = *(const float4*)(seq + rowoff[arow + 64] + k0 + acol);
        As[acol + 0][arow] = a0.x;
        As[acol + 1][arow] = a0.y;
        As[acol + 2][arow] = a0.z;
        As[acol + 3][arow] = a0.w;
        As[acol + 0][arow + 64] = a1.x;
        As[acol + 1][arow + 64] = a1.y;
        As[acol + 2][arow + 64] = a1.z;
        As[acol + 3][arow + 64] = a1.w;

        *(float4*)&Bs[brow    ][bcol] =
            *(const float4*)(W + (size_t)(k0 + brow)     * E_ + col0 + bcol);
        *(float4*)&Bs[brow + 8][bcol] =
            *(const float4*)(W + (size_t)(k0 + brow + 8) * E_ + col0 + bcol);

        __syncthreads();

#pragma unroll
        for (int k = 0; k < 16; k++) {
            float a[8], bb[8];
#pragma unroll
            for (int i = 0; i < 8; i++) a[i]  = As[k][ty * 8 + i];
#pragma unroll
            for (int j = 0; j < 8; j++) bb[j] = Bs[k][tx * 8 + j];
#pragma unroll
            for (int i = 0; i < 8; i++)
#pragma unroll
                for (int j = 0; j < 8; j++)
                    acc[i][j] += a[i] * bb[j];
        }
        __syncthreads();
    }

    float bv[8];
#pragma unroll
    for (int j = 0; j < 8; j++) bv[j] = bias[col0 + tx * 8 + j];

#pragma unroll
    for (int i = 0; i < 8; i++) {
        int m = row0 + ty * 8 + i;
        float* dst = g_lm + (size_t)m * E_ + col0 + tx * 8;
        float4 v0, v1;
        v0.x = acc[i][0] + bv[0];  v0.y = acc[i][1] + bv[1];
        v0.z = acc[i][2] + bv[2];  v0.w = acc[i][3] + bv[3];
        v1.x = acc[i][4] + bv[4];  v1.y = acc[i][5] + bv[5];
        v1.z = acc[i][6] + bv[6];  v1.w = acc[i][7] + bv[7];
        *(float4*)(dst)     = v0;
        *(float4*)(dst + 4) = v1;
    }
}

// ---------------------------------------------------------------------------
// Kernel 2: per-(b,p) LayerNorm (fused) + 64 candidate-embedding dot products.
// One block per row (2432 blocks), 256 threads = 8 warps x 8 candidates each.
// ---------------------------------------------------------------------------
__global__ void __launch_bounds__(256)
logits_kernel(const float* __restrict__ emb,
              const float* __restrict__ gamma,
              const float* __restrict__ beta,
              float* __restrict__ out)
{
    __shared__ __align__(16) float lm_s[E_];
    __shared__ float red[16];
    __shared__ float mu_s, rinv_s;

    const int bp   = blockIdx.x;
    const int tid  = threadIdx.x;
    const int wid  = tid >> 5;
    const int lane = tid & 31;

    const float* row = g_lm + (size_t)bp * E_;
    float x0 = row[tid];
    float x1 = row[tid + 256];
    float x2 = row[tid + 512];

    float s  = x0 + x1 + x2;
    float sq = x0 * x0 + x1 * x1 + x2 * x2;
#pragma unroll
    for (int o = 16; o; o >>= 1) {
        s  += __shfl_xor_sync(0xffffffffu, s,  o);
        sq += __shfl_xor_sync(0xffffffffu, sq, o);
    }
    if (lane == 0) { red[wid] = s; red[wid + 8] = sq; }
    __syncthreads();
    if (tid == 0) {
        float S = 0.f, SQ = 0.f;
#pragma unroll
        for (int w = 0; w < 8; w++) { S += red[w]; SQ += red[w + 8]; }
        float mu  = S * (1.0f / E_);
        float var = SQ * (1.0f / E_) - mu * mu;
        mu_s   = mu;
        rinv_s = rsqrtf(var + 1e-12f);
    }
    __syncthreads();
    const float mu = mu_s, rinv = rinv_s;

    lm_s[tid]       = (x0 - mu) * rinv * gamma[tid]       + beta[tid];
    lm_s[tid + 256] = (x1 - mu) * rinv * gamma[tid + 256] + beta[tid + 256];
    lm_s[tid + 512] = (x2 - mu) * rinv * gamma[tid + 512] + beta[tid + 512];
    __syncthreads();

    const float4* lp = (const float4*)lm_s;
    const int* crow = g_cand + bp * K_;

#pragma unroll
    for (int kk = 0; kk < 8; kk++) {
        int k = wid * 8 + kk;
        int cidx = crow[k];
        const float4* ep = (const float4*)(emb + (size_t)cidx * E_);
        float acc = 0.f;
#pragma unroll
        for (int j = 0; j < 6; j++) {
            float4 e = ep[j * 32 + lane];
            float4 l = lp[j * 32 + lane];
            acc += e.x * l.x + e.y * l.y + e.z * l.z + e.w * l.w;
        }
#pragma unroll
        for (int o = 16; o; o >>= 1)
            acc += __shfl_xor_sync(0xffffffffu, acc, o);
        if (lane == 0) out[(size_t)bp * K_ + k] = acc;
    }
}

// ---------------------------------------------------------------------------
extern "C" void kernel_launch(void* const* d_in, const int* in_sizes, int n_in,
                              void* d_out, int out_size)
{
    const float* seq   = (const float*)d_in[0];
    const int*   mraw  = (const int*)d_in[1];
    const int*   craw  = (const int*)d_in[2];
    const float* emb   = (const float*)d_in[3];
    const float* W     = (const float*)d_in[4];
    const float* bias  = (const float*)d_in[5];
    const float* gamma = (const float*)d_in[6];
    const float* beta  = (const float*)d_in[7];
    float*       out   = (float*)d_out;

    prep_detect_kernel<<<1, 256>>>(mraw, craw);
    prep_cand_kernel<<<(M_ * K_ + 255) / 256, 256>>>(craw);

    dim3 g1(E_ / 128, M_ / 128);   // 6 x 19
    gemm_gather_kernel<<<g1, 256>>>(seq, W, bias);
    logits_kernel<<<M_, 256>>>(emb, gamma, beta, out);
}

// round 3
// speedup vs baseline: 1.2584x; 1.2584x over previous
#include <cuda_runtime.h>
#include <cstdint>

// Problem constants (fixed shapes from reference)
#define B_  32
#define S_  512
#define H_  768
#define P_  76
#define K_  64
#define E_  768
#define M_  (B_ * P_)     // 2432 rows

#define BM 128
#define BN 96
#define BK 16

// Scratch
__device__ float g_lm[M_ * E_];          // 7.1 MB pre-LN dense output
__device__ int   g_m64;                  // masked_positions stored as int64?
__device__ int   g_c64;                  // candidate_sets stored as int64?

// ---------------------------------------------------------------------------
// Prologue: detect index dtype (int64 little-endian nonneg < 2^31 => every
// odd 32-bit word is 0).  512 samples each => false-positive prob ~0.
// ---------------------------------------------------------------------------
__global__ void prep_detect_kernel(const int* __restrict__ mraw,
                                   const int* __restrict__ craw)
{
    __shared__ int nzm, nzc;
    if (threadIdx.x == 0) { nzm = 0; nzc = 0; }
    __syncthreads();
    for (int i = threadIdx.x; i < 512; i += 256) {
        if (mraw[2 * i + 1] != 0) atomicOr(&nzm, 1);
        if (craw[2 * i + 1] != 0) atomicOr(&nzc, 1);
    }
    __syncthreads();
    if (threadIdx.x == 0) { g_m64 = (nzm == 0); g_c64 = (nzc == 0); }
}

// ---------------------------------------------------------------------------
// Kernel 1: gathered-A SGEMM via packed fp32x2 FMA (FFMA2, 2x FFMA rate).
// 128x96 block tile (19 x 8 = 152 CTAs -> one full wave on 148 SMs),
// BK=16, 256 threads, 8-row x 6-col (3 f32x2 pairs) per-thread microtile.
// Double-buffered smem + register prefetch: one __syncthreads per K-step.
// ---------------------------------------------------------------------------
__global__ void __launch_bounds__(256)
gemm_gather_kernel(const float* __restrict__ seq,
                   const int*   __restrict__ mraw,
                   const float* __restrict__ W,
                   const float* __restrict__ bias)
{
    __shared__ float As[2][BK][132];      // padded, A stored k-major
    __shared__ float Bs[2][BK][BN];
    __shared__ unsigned rowoff[BM];

    const int tid  = threadIdx.x;
    const int row0 = blockIdx.y * BM;
    const int col0 = blockIdx.x * BN;

    if (tid < BM) {
        int m   = row0 + tid;
        int b   = m / P_;
        int pos = g_m64 ? mraw[2 * m] : mraw[m];
        rowoff[tid] = (unsigned)(b * S_ + pos) * H_;
    }
    __syncthreads();

    // Loader indices
    const int arow = tid >> 2;            // 0..63
    const int acol = (tid & 3) * 4;       // 0,4,8,12
    // B: 3 float2 per thread over 16x96 tile (768 float2 elements)
    int bkr[3], bc2[3];
#pragma unroll
    for (int i = 0; i < 3; i++) {
        int l  = tid + i * 256;
        bkr[i] = l / 48;                  // k-row 0..15
        bc2[i] = (l % 48) * 2;            // col 0..94 (even)
    }

    const int ty = tid >> 4;              // 0..15  -> rows ty*8..+7
    const int tx = tid & 15;              // 0..15  -> cols tx*6..+5

    unsigned long long acc[8][3];
#pragma unroll
    for (int i = 0; i < 8; i++)
#pragma unroll
        for (int j = 0; j < 3; j++) acc[i][j] = 0ULL;

    // Prologue: load k-tile 0 into buffer 0
    {
        float4 a0 = *(const float4*)(seq + rowoff[arow]      + acol);
        float4 a1 = *(const float4*)(seq + rowoff[arow + 64] + acol);
        As[0][acol + 0][arow] = a0.x;  As[0][acol + 1][arow] = a0.y;
        As[0][acol + 2][arow] = a0.z;  As[0][acol + 3][arow] = a0.w;
        As[0][acol + 0][arow + 64] = a1.x;  As[0][acol + 1][arow + 64] = a1.y;
        As[0][acol + 2][arow + 64] = a1.z;  As[0][acol + 3][arow + 64] = a1.w;
#pragma unroll
        for (int i = 0; i < 3; i++)
            *(float2*)&Bs[0][bkr[i]][bc2[i]] =
                *(const float2*)(W + (size_t)bkr[i] * E_ + col0 + bc2[i]);
    }
    __syncthreads();

    const int NIT = H_ / BK;              // 48
    for (int it = 0; it < NIT; ++it) {
        const int p = it & 1;

        float4 pa0, pa1;
        float2 pb[3];
        if (it < NIT - 1) {
            const int k0 = (it + 1) * BK;
            pa0 = *(const float4*)(seq + rowoff[arow]      + k0 + acol);
            pa1 = *(const float4*)(seq + rowoff[arow + 64] + k0 + acol);
#pragma unroll
            for (int i = 0; i < 3; i++)
                pb[i] = *(const float2*)(W + (size_t)(k0 + bkr[i]) * E_
                                           + col0 + bc2[i]);
        }

#pragma unroll
        for (int k = 0; k < BK; ++k) {
            unsigned long long bv0 = *(const unsigned long long*)&Bs[p][k][tx * 6 + 0];
            unsigned long long bv1 = *(const unsigned long long*)&Bs[p][k][tx * 6 + 2];
            unsigned long long bv2 = *(const unsigned long long*)&Bs[p][k][tx * 6 + 4];
#pragma unroll
            for (int i = 0; i < 8; ++i) {
                unsigned au = __float_as_uint(As[p][k][ty * 8 + i]);
                unsigned long long ad;
                asm("mov.b64 %0, {%1, %1};" : "=l"(ad) : "r"(au));
                asm("fma.rn.f32x2 %0, %1, %2, %0;" : "+l"(acc[i][0]) : "l"(ad), "l"(bv0));
                asm("fma.rn.f32x2 %0, %1, %2, %0;" : "+l"(acc[i][1]) : "l"(ad), "l"(bv1));
                asm("fma.rn.f32x2 %0, %1, %2, %0;" : "+l"(acc[i][2]) : "l"(ad), "l"(bv2));
            }
        }

        if (it < NIT - 1) {
            const int q = 1 - p;
            As[q][acol + 0][arow] = pa0.x;  As[q][acol + 1][arow] = pa0.y;
            As[q][acol + 2][arow] = pa0.z;  As[q][acol + 3][arow] = pa0.w;
            As[q][acol + 0][arow + 64] = pa1.x;  As[q][acol + 1][arow + 64] = pa1.y;
            As[q][acol + 2][arow + 64] = pa1.z;  As[q][acol + 3][arow + 64] = pa1.w;
#pragma unroll
            for (int i = 0; i < 3; i++)
                *(float2*)&Bs[q][bkr[i]][bc2[i]] = pb[i];
        }
        __syncthreads();
    }

    // Epilogue: + bias, write to scratch
    float2 bb[3];
#pragma unroll
    for (int j = 0; j < 3; j++)
        bb[j] = *(const float2*)(bias + col0 + tx * 6 + 2 * j);

#pragma unroll
    for (int i = 0; i < 8; i++) {
        int m = row0 + ty * 8 + i;
        float* dst = g_lm + (size_t)m * E_ + col0 + tx * 6;
#pragma unroll
        for (int j = 0; j < 3; j++) {
            unsigned lo, hi;
            asm("mov.b64 {%0, %1}, %2;" : "=r"(lo), "=r"(hi) : "l"(acc[i][j]));
            float2 v;
            v.x = __uint_as_float(lo) + bb[j].x;
            v.y = __uint_as_float(hi) + bb[j].y;
            *(float2*)(dst + 2 * j) = v;
        }
    }
}

// ---------------------------------------------------------------------------
// Kernel 2: per-(b,p) LayerNorm (fused) + 64 candidate-embedding dot products.
// One block per row (2432 blocks), 256 threads = 8 warps x 8 candidates.
// Candidates processed in pairs for 2x memory-level parallelism.
// ---------------------------------------------------------------------------
__global__ void __launch_bounds__(256)
logits_kernel(const int*   __restrict__ craw,
              const float* __restrict__ emb,
              const float* __restrict__ gamma,
              const float* __restrict__ beta,
              float* __restrict__ out)
{
    __shared__ __align__(16) float lm_s[E_];
    __shared__ float red[16];
    __shared__ float mu_s, rinv_s;

    const int bp   = blockIdx.x;
    const int tid  = threadIdx.x;
    const int wid  = tid >> 5;
    const int lane = tid & 31;
    const int c64  = g_c64;

    const float* row = g_lm + (size_t)bp * E_;
    float x0 = row[tid];
    float x1 = row[tid + 256];
    float x2 = row[tid + 512];

    float s  = x0 + x1 + x2;
    float sq = x0 * x0 + x1 * x1 + x2 * x2;
#pragma unroll
    for (int o = 16; o; o >>= 1) {
        s  += __shfl_xor_sync(0xffffffffu, s,  o);
        sq += __shfl_xor_sync(0xffffffffu, sq, o);
    }
    if (lane == 0) { red[wid] = s; red[wid + 8] = sq; }
    __syncthreads();
    if (tid == 0) {
        float S = 0.f, SQ = 0.f;
#pragma unroll
        for (int w = 0; w < 8; w++) { S += red[w]; SQ += red[w + 8]; }
        float mu  = S * (1.0f / E_);
        float var = SQ * (1.0f / E_) - mu * mu;
        mu_s   = mu;
        rinv_s = rsqrtf(var + 1e-12f);
    }
    __syncthreads();
    const float mu = mu_s, rinv = rinv_s;

    lm_s[tid]       = (x0 - mu) * rinv * gamma[tid]       + beta[tid];
    lm_s[tid + 256] = (x1 - mu) * rinv * gamma[tid + 256] + beta[tid + 256];
    lm_s[tid + 512] = (x2 - mu) * rinv * gamma[tid + 512] + beta[tid + 512];
    __syncthreads();

    const float4* lp = (const float4*)lm_s;

#pragma unroll
    for (int kk = 0; kk < 4; kk++) {
        int k  = wid * 8 + kk * 2;
        int i0 = bp * K_ + k;
        int c0 = c64 ? craw[2 * i0]       : craw[i0];
        int c1 = c64 ? craw[2 * i0 + 2]   : craw[i0 + 1];
        const float4* e0 = (const float4*)(emb + (size_t)c0 * E_);
        const float4* e1 = (const float4*)(emb + (size_t)c1 * E_);
        float acc0 = 0.f, acc1 = 0.f;
#pragma unroll
        for (int j = 0; j < 6; j++) {
            float4 l  = lp[j * 32 + lane];
            float4 a  = e0[j * 32 + lane];
            float4 b2 = e1[j * 32 + lane];
            acc0 += a.x  * l.x + a.y  * l.y + a.z  * l.z + a.w  * l.w;
            acc1 += b2.x * l.x + b2.y * l.y + b2.z * l.z + b2.w * l.w;
        }
#pragma unroll
        for (int o = 16; o; o >>= 1) {
            acc0 += __shfl_xor_sync(0xffffffffu, acc0, o);
            acc1 += __shfl_xor_sync(0xffffffffu, acc1, o);
        }
        if (lane == 0) {
            out[i0]     = acc0;
            out[i0 + 1] = acc1;
        }
    }
}

// ---------------------------------------------------------------------------
extern "C" void kernel_launch(void* const* d_in, const int* in_sizes, int n_in,
                              void* d_out, int out_size)
{
    const float* seq   = (const float*)d_in[0];
    const int*   mraw  = (const int*)d_in[1];
    const int*   craw  = (const int*)d_in[2];
    const float* emb   = (const float*)d_in[3];
    const float* W     = (const float*)d_in[4];
    const float* bias  = (const float*)d_in[5];
    const float* gamma = (const float*)d_in[6];
    const float* beta  = (const float*)d_in[7];
    float*       out   = (float*)d_out;

    prep_detect_kernel<<<1, 256>>>(mraw, craw);

    dim3 g1(E_ / BN, M_ / BM);   // 8 x 19 = 152 CTAs
    gemm_gather_kernel<<<g1, 256>>>(seq, mraw, W, bias);
    logits_kernel<<<M_, 256>>>(craw, emb, gamma, beta, out);
}